// round 13
// baseline (speedup 1.0000x reference)
#include <cuda_runtime.h>
#include <cstdint>

// Problem constants
#define POOL 7
#define NUM_ROIS 256
#define H_IMG 128
#define W_IMG 128
#define SCALE (1.0f / 16.0f)
#define NCELL (POOL * POOL)                 // 49
#define TOTAL (NUM_ROIS * NCELL)            // 12544
#define GRIDB 1184                          // 148 SMs * 8 resident CTAs

// Persistent-CTA, software-pipelined ROI bilinear pooling.
// Each CTA grid-strides over ~11 (roi,cell) work items; the 4 corner loads of
// item i+1 are issued BEFORE computing item i, so steady-state warps always
// have independent loads in flight (no exposed per-CTA latency tail, no
// wave-transition churn). Dead corners (zero lerp weight / clamped duplicate)
// are SEL-redirected to the live corner (same cache line, zero extra L2
// bytes, bit-identical: v + 0*(x - v) == v). Streaming stores keep the 51 MB
// output from evicting the L2-resident img.

struct CellCtx {
    int   pix00, pix01, pix10, pix11;   // pixel index gy*W + gx
    float tx, ty;
};

__device__ __forceinline__ CellCtx setup_cell(const float* __restrict__ rois, int idx)
{
    CellCtx s;
    const int cell = idx % NCELL;
    const int roi  = idx / NCELL;
    const int iy   = cell / POOL;
    const int ix   = cell % POOL;

    const float4 r = ((const float4*)rois)[roi];
    const int x0 = (int)(r.x * SCALE);
    const int y0 = (int)(r.y * SCALE);
    const int w  = (int)(r.z * SCALE);
    const int h  = (int)(r.w * SCALE);

    // Match reference arithmetic order exactly
    const float sy = (float)iy * ((float)h / (float)POOL);
    const float sx = (float)ix * ((float)w / (float)POOL);
    const float fy = floorf(sy);
    const float fx = floorf(sx);
    s.ty = sy - fy;
    s.tx = sx - fx;
    const int y_lo = (int)fy;
    const int x_lo = (int)fx;
    const int y_hi = min(y_lo + 1, max(h - 1, 0));
    const int x_hi = min(x_lo + 1, max(w - 1, 0));
    const int gy0 = min(max(y0 + y_lo, 0), H_IMG - 1);
    int       gy1 = min(max(y0 + y_hi, 0), H_IMG - 1);
    const int gx0 = min(max(x0 + x_lo, 0), W_IMG - 1);
    int       gx1 = min(max(x0 + x_hi, 0), W_IMG - 1);

    // Branchless dead-load redirection.
    gx1 = (s.tx != 0.0f) ? gx1 : gx0;
    gy1 = (s.ty != 0.0f) ? gy1 : gy0;

    s.pix00 = gy0 * W_IMG + gx0;
    s.pix01 = gy0 * W_IMG + gx1;
    s.pix10 = gy1 * W_IMG + gx0;
    s.pix11 = gy1 * W_IMG + gx1;
    return s;
}

__global__ void __launch_bounds__(256)
roi_pool_kernel(const float* __restrict__ img,
                const float* __restrict__ rois,
                float* __restrict__ out)
{
    const int c = threadIdx.x;          // float4 channel chunk 0..255
    float4* out4 = (float4*)out;

    int idx = blockIdx.x;
    if (idx >= TOTAL) return;

    // Prologue: issue loads for the first item.
    CellCtx cur = setup_cell(rois, idx);
    float4 v00 = __ldg((const float4*)(img + ((size_t)cur.pix00 << 10)) + c);
    float4 v01 = __ldg((const float4*)(img + ((size_t)cur.pix01 << 10)) + c);
    float4 v10 = __ldg((const float4*)(img + ((size_t)cur.pix10 << 10)) + c);
    float4 v11 = __ldg((const float4*)(img + ((size_t)cur.pix11 << 10)) + c);

    while (true) {
        const int nidx = idx + GRIDB;
        const bool has_next = (nidx < TOTAL);

        // Prefetch next item's corners (clamped index: harmless reload if last).
        const CellCtx nxt = setup_cell(rois, has_next ? nidx : idx);
        const float4 n00 = __ldg((const float4*)(img + ((size_t)nxt.pix00 << 10)) + c);
        const float4 n01 = __ldg((const float4*)(img + ((size_t)nxt.pix01 << 10)) + c);
        const float4 n10 = __ldg((const float4*)(img + ((size_t)nxt.pix10 << 10)) + c);
        const float4 n11 = __ldg((const float4*)(img + ((size_t)nxt.pix11 << 10)) + c);

        // Compute current item (reference arithmetic order).
        const float tx = cur.tx, ty = cur.ty;
        float4 o;
        {
            float top = v00.x + tx * (v01.x - v00.x);
            float bot = v10.x + tx * (v11.x - v10.x);
            o.x = top + ty * (bot - top);
        }
        {
            float top = v00.y + tx * (v01.y - v00.y);
            float bot = v10.y + tx * (v11.y - v10.y);
            o.y = top + ty * (bot - top);
        }
        {
            float top = v00.z + tx * (v01.z - v00.z);
            float bot = v10.z + tx * (v11.z - v10.z);
            o.z = top + ty * (bot - top);
        }
        {
            float top = v00.w + tx * (v01.w - v00.w);
            float bot = v10.w + tx * (v11.w - v10.w);
            o.w = top + ty * (bot - top);
        }

        // Streaming store (evict-first): out never displaces img in L2.
        __stcs(out4 + (((size_t)idx) << 8) + c, o);

        if (!has_next) break;
        idx = nidx;
        cur = nxt;
        v00 = n00; v01 = n01; v10 = n10; v11 = n11;
    }
}

extern "C" void kernel_launch(void* const* d_in, const int* in_sizes, int n_in,
                              void* d_out, int out_size)
{
    const float* img  = (const float*)d_in[0];
    const float* rois = (const float*)d_in[1];
    float* out = (float*)d_out;

    roi_pool_kernel<<<GRIDB, 256>>>(img, rois, out);
}

// round 15
// speedup vs baseline: 1.0634x; 1.0634x over previous
#include <cuda_runtime.h>
#include <cstdint>

// Problem constants
#define POOL 7
#define NUM_ROIS 256
#define H_IMG 128
#define W_IMG 128
#define SCALE (1.0f / 16.0f)

// One CTA per (roi, cell), 256 threads, one float4 of channels per thread.
// R8 compute structure (batched LDG.128 reads + branchless dead-corner
// redirect), but the 4 KB output tile is staged in SMEM and written by ONE
// cp.async.bulk.global (bulk-async engine, UBLKCP.G.S): a single full-line
// 4 KB transfer SMEM->L2, bypassing the per-thread STG/L1tex write path that
// every previous kernel shape shared.
__global__ void __launch_bounds__(256, 8)
roi_pool_kernel(const float* __restrict__ img,
                const float* __restrict__ rois,
                float* __restrict__ out)
{
    __shared__ alignas(128) float4 sbuf[256];   // 4 KB staging tile

    const int cell = blockIdx.x;   // 0..48
    const int roi  = blockIdx.y;   // 0..255
    const int iy   = cell / POOL;
    const int ix   = cell % POOL;

    const float4 r = *(const float4*)(rois + roi * 4);
    const int x0 = (int)(r.x * SCALE);
    const int y0 = (int)(r.y * SCALE);
    const int w  = (int)(r.z * SCALE);
    const int h  = (int)(r.w * SCALE);

    // Match reference arithmetic order exactly
    const float sy = (float)iy * ((float)h / (float)POOL);
    const float sx = (float)ix * ((float)w / (float)POOL);
    const float fy = floorf(sy);
    const float fx = floorf(sx);
    const float ty = sy - fy;
    const float tx = sx - fx;
    const int y_lo = (int)fy;
    const int x_lo = (int)fx;
    const int y_hi = min(y_lo + 1, max(h - 1, 0));
    const int x_hi = min(x_lo + 1, max(w - 1, 0));
    const int gy0 = min(max(y0 + y_lo, 0), H_IMG - 1);
    int       gy1 = min(max(y0 + y_hi, 0), H_IMG - 1);
    const int gx0 = min(max(x0 + x_lo, 0), W_IMG - 1);
    int       gx1 = min(max(x0 + x_hi, 0), W_IMG - 1);

    // Branchless dead-load redirection (SEL): zero-weight / clamped-duplicate
    // corner aliases the live one (same cache line; v + 0*(x - v) == v).
    gx1 = (tx != 0.0f) ? gx1 : gx0;
    gy1 = (ty != 0.0f) ? gy1 : gy0;

    const float4* p00 = (const float4*)(img + ((size_t)(gy0 * W_IMG + gx0) << 10));
    const float4* p01 = (const float4*)(img + ((size_t)(gy0 * W_IMG + gx1) << 10));
    const float4* p10 = (const float4*)(img + ((size_t)(gy1 * W_IMG + gx0) << 10));
    const float4* p11 = (const float4*)(img + ((size_t)(gy1 * W_IMG + gx1) << 10));

    const int c = threadIdx.x;  // float4 index 0..255

    const float4 v00 = p00[c];
    const float4 v01 = p01[c];
    const float4 v10 = p10[c];
    const float4 v11 = p11[c];

    float4 o;
    {
        float top = v00.x + tx * (v01.x - v00.x);
        float bot = v10.x + tx * (v11.x - v10.x);
        o.x = top + ty * (bot - top);
    }
    {
        float top = v00.y + tx * (v01.y - v00.y);
        float bot = v10.y + tx * (v11.y - v10.y);
        o.y = top + ty * (bot - top);
    }
    {
        float top = v00.z + tx * (v01.z - v00.z);
        float bot = v10.z + tx * (v11.z - v10.z);
        o.z = top + ty * (bot - top);
    }
    {
        float top = v00.w + tx * (v01.w - v00.w);
        float bot = v10.w + tx * (v11.w - v10.w);
        o.w = top + ty * (bot - top);
    }

    sbuf[c] = o;
    __syncthreads();

    if (c == 0) {
        // Make generic-proxy STS visible to the async (bulk) proxy.
        asm volatile("fence.proxy.async.shared::cta;" ::: "memory");
        const float* dst = out + (((size_t)(roi * (POOL * POOL) + cell)) << 10);
        const uint32_t src = (uint32_t)__cvta_generic_to_shared(sbuf);
        asm volatile(
            "cp.async.bulk.global.shared::cta.bulk_group [%0], [%1], %2;"
            :: "l"(dst), "r"(src), "r"(4096u) : "memory");
        asm volatile("cp.async.bulk.commit_group;" ::: "memory");
        // Copy must finish reading SMEM before the CTA retires.
        asm volatile("cp.async.bulk.wait_group 0;" ::: "memory");
    }
}

extern "C" void kernel_launch(void* const* d_in, const int* in_sizes, int n_in,
                              void* d_out, int out_size)
{
    const float* img  = (const float*)d_in[0];
    const float* rois = (const float*)d_in[1];
    float* out = (float*)d_out;

    dim3 grid(POOL * POOL, NUM_ROIS);
    roi_pool_kernel<<<grid, 256>>>(img, rois, out);
}